// round 1
// baseline (speedup 1.0000x reference)
#include <cuda_runtime.h>

#define FULLMASK 0xFFFFFFFFu

// One warp per row. Each iteration handles 128 consecutive elements
// (4 per lane via float4). Sequential Bayesian recurrence carried in
// (s_carry, D_carry); intra-iteration prefixes via warp shfl scans.
__global__ void __launch_bounds__(128)
bbm_kernel(const float* __restrict__ obs,
           const float* __restrict__ alpha1,
           const float* __restrict__ beta1,
           const float* __restrict__ alpha2,
           const float* __restrict__ beta2,
           const float* __restrict__ mixw,
           float* __restrict__ out,
           int B, int T)
{
    const int wid  = threadIdx.x >> 5;
    const int lane = threadIdx.x & 31;
    const int row  = blockIdx.x * (blockDim.x >> 5) + wid;
    if (row >= B) return;

    const float a1c = __ldg(alpha1 + row);
    const float b1c = __ldg(beta1  + row);
    const float a2c = __ldg(alpha2 + row);
    const float b2c = __ldg(beta2  + row);
    const float ab1 = a1c + b1c;   // alpha1 + beta1
    const float ab2 = a2c + b2c;   // alpha2 + beta2
    const float w   = __ldg(mixw);
    const float omw = 1.0f - w;

    const float4* __restrict__ orow =
        reinterpret_cast<const float4*>(obs + (size_t)row * (size_t)T);

    const size_t NT = (size_t)B * (size_t)T;
    float* o_a1 = out + (size_t)row * (size_t)T;
    float* o_b1 = o_a1 + NT;
    float* o_a2 = o_b1 + NT;
    float* o_b2 = o_a2 + NT;
    float* o_pm = o_b2 + NT;

    int   s_carry = 0;     // successes before current position
    float D_carry = 0.0f;  // D(t) = clog2(t) - clog1(t); D(0) = 0 exactly

    const int iters = T >> 7;  // 128 elements per warp-iteration
    float4 v = orow[lane];     // software-pipelined load

    for (int it = 0; it < iters; ++it) {
        float4 vnext;
        if (it + 1 < iters) vnext = orow[(it + 1) * 32 + lane];

        int bits[4];
        bits[0] = v.x > 0.5f; bits[1] = v.y > 0.5f;
        bits[2] = v.z > 0.5f; bits[3] = v.w > 0.5f;
        const int cnt = bits[0] + bits[1] + bits[2] + bits[3];

        // warp inclusive scan of per-lane success counts
        int inc = cnt;
        #pragma unroll
        for (int d = 1; d < 32; d <<= 1) {
            int n = __shfl_up_sync(FULLMASK, inc, d);
            if (lane >= d) inc += n;
        }
        const int s0      = s_carry + (inc - cnt);  // exclusive prefix
        const int cntTot  = __shfl_sync(FULLMASK, inc, 31);

        const int t0 = (it << 7) + (lane << 2);

        // Pass 1: per-element log-ratio deltas + local prefix.
        // Step t -> t+1:
        //   D += log( (a2+x)*(ab1+t) / ((a1+x)*(ab2+t)) ),  x = s (obs=1) or f (obs=0)
        float dpre[4];
        float dacc = 0.0f;
        int ss = s0;
        #pragma unroll
        for (int j = 0; j < 4; ++j) {
            const float tf = (float)(t0 + j);
            const float sf = (float)ss;
            const float ff = tf - sf;     // exact: small integers in fp32
            float num, den;
            if (bits[j]) { num = a2c + sf; den = a1c + sf; }
            else         { num = b2c + ff; den = b1c + ff; }
            const float g1 = ab1 + tf;
            const float g2 = ab2 + tf;
            dpre[j] = dacc;               // prefix BEFORE element j
            dacc += __logf(__fdividef(num * g1, den * g2));
            ss += bits[j];
        }

        // warp inclusive scan of per-lane D deltas
        float finc = dacc;
        #pragma unroll
        for (int d = 1; d < 32; d <<= 1) {
            float n = __shfl_up_sync(FULLMASK, finc, d);
            if (lane >= d) finc += n;
        }
        const float Dbase = D_carry + (finc - dacc);  // exclusive prefix
        const float Dtot  = __shfl_sync(FULLMASK, finc, 31);

        // Pass 2: outputs. a/b planes are exact; pm = w / (w + (1-w)*exp(D))
        float oa1[4], ob1[4], oa2[4], ob2[4], opm[4];
        ss = s0;
        #pragma unroll
        for (int j = 0; j < 4; ++j) {
            const float tf = (float)(t0 + j);
            const float sf = (float)ss;
            const float ff = tf - sf;
            oa1[j] = a1c + sf;
            ob1[j] = b1c + ff;
            oa2[j] = a2c + sf;
            ob2[j] = b2c + ff;
            const float E = __expf(Dbase + dpre[j]);
            opm[j] = __fdividef(w, fmaf(omw, E, w));
            ss += bits[j];
        }

        *reinterpret_cast<float4*>(o_a1 + t0) = make_float4(oa1[0], oa1[1], oa1[2], oa1[3]);
        *reinterpret_cast<float4*>(o_b1 + t0) = make_float4(ob1[0], ob1[1], ob1[2], ob1[3]);
        *reinterpret_cast<float4*>(o_a2 + t0) = make_float4(oa2[0], oa2[1], oa2[2], oa2[3]);
        *reinterpret_cast<float4*>(o_b2 + t0) = make_float4(ob2[0], ob2[1], ob2[2], ob2[3]);
        *reinterpret_cast<float4*>(o_pm + t0) = make_float4(opm[0], opm[1], opm[2], opm[3]);

        s_carry += cntTot;
        D_carry += Dtot;
        v = vnext;
    }
}

extern "C" void kernel_launch(void* const* d_in, const int* in_sizes, int n_in,
                              void* d_out, int out_size)
{
    const float* obs = (const float*)d_in[0];
    const float* a1  = (const float*)d_in[1];
    const float* b1  = (const float*)d_in[2];
    const float* a2  = (const float*)d_in[3];
    const float* b2  = (const float*)d_in[4];
    const float* mw  = (const float*)d_in[5];

    const int B = in_sizes[1];
    const int T = in_sizes[0] / B;

    const int warpsPerBlock = 4;
    dim3 block(32 * warpsPerBlock);
    dim3 grid((B + warpsPerBlock - 1) / warpsPerBlock);
    bbm_kernel<<<grid, block>>>(obs, a1, b1, a2, b2, mw, (float*)d_out, B, T);
}